// round 3
// baseline (speedup 1.0000x reference)
#include <cuda_runtime.h>
#include <cuda_bf16.h>
#include <math.h>

// Box-embedding conditional-probability loss. B pairs, D=128.
// R3: latency-bound (issue=50%, occ=54%) -> trade per-thread work for
// occupancy. 16 lanes/pair (2 pairs/warp), 8 dims/lane, 8 LDG.128/thread,
// __launch_bounds__(256,8) to force <=32 regs -> 64 warps/SM.

#define EPS_F 1e-8f

static __device__ __forceinline__ float split_mant(float p, int& e) {
    int ib = __float_as_int(p);
    e += ((ib >> 23) & 0xFF) - 127;
    return __int_as_float((ib & 0x007FFFFF) | 0x3F800000);  // [1,2)
}

__global__ void __launch_bounds__(256, 8)
box_pair_kernel(const int* __restrict__ t1x,
                const int* __restrict__ t2x,
                const float* __restrict__ min_tab,
                const float* __restrict__ dlt_tab,
                float* __restrict__ out_pos,
                float* __restrict__ out_neg,
                int B)
{
    const float MIN_MEAN   = (float)((0.0001 + 0.01) / 2.0);
    const float MIN_VAR    = (float)(0.01 - (0.0001 + 0.01) / 2.0);
    const float DELTA_MEAN = (float)((0.9 + 0.999) / 2.0);
    const float DELTA_VAR  = (float)(0.999 - (0.9 + 0.999) / 2.0);

    int gtid = blockIdx.x * blockDim.x + threadIdx.x;
    int pair = gtid >> 4;           // 16 lanes per pair
    int sub  = threadIdx.x & 15;
    if (pair >= B) return;

    int i1 = __ldg(t1x + pair);
    int i2 = __ldg(t2x + pair);

    // lane reads float4 chunks sub and sub+16 of each 32-float4 row:
    // 16 lanes x 16B = 256B contiguous -> perfectly coalesced.
    const float4* m1p = (const float4*)(min_tab + (size_t)i1 * 128) + sub;
    const float4* d1p = (const float4*)(dlt_tab + (size_t)i1 * 128) + sub;
    const float4* m2p = (const float4*)(min_tab + (size_t)i2 * 128) + sub;
    const float4* d2p = (const float4*)(dlt_tab + (size_t)i2 * 128) + sub;

    float p1 = 1.0f, p2 = 1.0f, pm = 1.0f, pj = 1.0f;
    int   E1 = 0, E2 = 0, EM = 0, EJ = 0;
    float mr = 3.4e38f;   // min raw meet extent over my dims

#pragma unroll
    for (int c = 0; c < 2; c++) {
        float4 m1 = __ldg(m1p + c * 16);
        float4 d1 = __ldg(d1p + c * 16);
        float4 m2 = __ldg(m2p + c * 16);
        float4 d2 = __ldg(d2p + c * 16);

        const float* m1v = &m1.x;
        const float* d1v = &d1.x;
        const float* m2v = &m2.x;
        const float* d2v = &d2.x;

#pragma unroll
        for (int j = 0; j < 4; j++) {
            float a  = fmaf(m1v[j], MIN_VAR, MIN_MEAN);     // t1_min
            float da = fmaf(d1v[j], DELTA_VAR, DELTA_MEAN); // t1 extent
            float c0 = fmaf(m2v[j], MIN_VAR, MIN_MEAN);     // t2_min
            float dc = fmaf(d2v[j], DELTA_VAR, DELTA_MEAN); // t2 extent
            float b  = a + da;                              // t1_max
            float d  = c0 + dc;                             // t2_max

            float jmin = fminf(a, c0);
            float jmax = fmaxf(b, d);
            float ej   = jmax - jmin;                 // join extent
            float em   = (da + dc) - ej;              // meet extent (identity)

            mr = fminf(mr, em);
            p1 *= da;
            p2 *= dc;
            pj *= ej;
            pm *= fmaxf(em, EPS_F);
        }
        // only pm can underflow (4 clamped dims -> 1e-32); renorm per chunk
        pm = split_mant(pm, EM);
    }

    // per-lane split keeps cross-lane products in fp32 range
    p1 = split_mant(p1, E1);
    p2 = split_mant(p2, E2);
    pj = split_mant(pj, EJ);

    // pack exponents: 16-bit fields, bias 2048 (16-lane sums < 65536)
    unsigned pk0 = (unsigned)(E1 + 2048) | ((unsigned)(E2 + 2048) << 16);
    unsigned pk1 = (unsigned)(EM + 2048) | ((unsigned)(EJ + 2048) << 16);

    const unsigned FULL = 0xFFFFFFFFu;
#pragma unroll
    for (int off = 8; off > 0; off >>= 1) {
        p1  *= __shfl_xor_sync(FULL, p1, off);
        p2  *= __shfl_xor_sync(FULL, p2, off);
        pm  *= __shfl_xor_sync(FULL, pm, off);
        pj  *= __shfl_xor_sync(FULL, pj, off);
        pk0 += __shfl_xor_sync(FULL, pk0, off);
        pk1 += __shfl_xor_sync(FULL, pk1, off);
    }

    // disjoint = any lane in my 16-lane group saw em <= 0
    unsigned ball = __ballot_sync(FULL, mr <= 0.0f);
    bool disjoint = ((ball >> (threadIdx.x & 16)) & 0xFFFFu) != 0u;

    if (sub == 0) {
        const int BIAS16 = 16 * 2048;
        int e1s = (int)(pk0 & 0xFFFFu) - BIAS16;
        int e2s = (int)(pk0 >> 16)     - BIAS16;
        int ems = (int)(pk1 & 0xFFFFu) - BIAS16;
        int ejs = (int)(pk1 >> 16)     - BIAS16;

        const float LN2 = 0.69314718055994530942f;
        float t1_log   = logf(p1) + (float)e1s * LN2;
        float t2_log   = logf(p2) + (float)e2s * LN2;
        float meet_log = logf(pm) + (float)ems * LN2;
        float join_log = logf(pj) + (float)ejs * LN2;

        float cond = meet_log - t2_log;   // log P(t1|t2)

        float posv, negv;
        if (disjoint) {
            posv = join_log - t1_log;
            negv = 0.0f;
        } else {
            posv = -cond;
            negv = -logf(fmaxf(1.0f - expf(cond), EPS_F));
        }
        out_pos[pair] = posv;
        out_neg[pair] = negv;
    }
}

extern "C" void kernel_launch(void* const* d_in, const int* in_sizes, int n_in,
                              void* d_out, int out_size) {
    const int*   t1x    = (const int*)d_in[0];
    const int*   t2x    = (const int*)d_in[1];
    const float* min_tb = (const float*)d_in[2];
    const float* dlt_tb = (const float*)d_in[3];

    int B = in_sizes[0];
    float* out_pos = (float*)d_out;
    float* out_neg = (float*)d_out + B;

    // 16 lanes per pair, 16 pairs per 256-thread block
    int pairs_per_block = 16;
    int grid = (B + pairs_per_block - 1) / pairs_per_block;
    box_pair_kernel<<<grid, 256>>>(t1x, t2x, min_tb, dlt_tb, out_pos, out_neg, B);
}

// round 4
// speedup vs baseline: 1.2912x; 1.2912x over previous
#include <cuda_runtime.h>
#include <cuda_bf16.h>
#include <math.h>

// Box-embedding conditional-probability loss. B pairs, D=128.
// R4: R2 shape (8 lanes/pair, best so far) + two cuts:
//  - ratio reduction: outputs only need meet-t2 and join-t1 log-differences,
//    so reduce rm=pm/p2, rj=pj/p1 (+1 exponent int) -> 3 values instead of 6.
//  - __launch_bounds__(256,7): <=36 regs -> ~56 warps/SM for latency hiding
//    at unchanged instruction count.

#define EPS_F 1e-8f

static __device__ __forceinline__ float split_mant(float p, int& e) {
    int ib = __float_as_int(p);
    e += ((ib >> 23) & 0xFF) - 127;
    return __int_as_float((ib & 0x007FFFFF) | 0x3F800000);  // [1,2)
}

__global__ void __launch_bounds__(256, 7)
box_pair_kernel(const int* __restrict__ t1x,
                const int* __restrict__ t2x,
                const float* __restrict__ min_tab,
                const float* __restrict__ dlt_tab,
                float* __restrict__ out_pos,
                float* __restrict__ out_neg,
                int B)
{
    const float MIN_MEAN   = (float)((0.0001 + 0.01) / 2.0);
    const float MIN_VAR    = (float)(0.01 - (0.0001 + 0.01) / 2.0);
    const float DELTA_MEAN = (float)((0.9 + 0.999) / 2.0);
    const float DELTA_VAR  = (float)(0.999 - (0.9 + 0.999) / 2.0);

    int gtid = blockIdx.x * blockDim.x + threadIdx.x;
    int pair = gtid >> 3;           // 8 lanes per pair
    int sub  = threadIdx.x & 7;
    if (pair >= B) return;

    int i1 = __ldg(t1x + pair);
    int i2 = __ldg(t2x + pair);

    const float4* m1p = (const float4*)(min_tab + (size_t)i1 * 128) + sub;
    const float4* d1p = (const float4*)(dlt_tab + (size_t)i1 * 128) + sub;
    const float4* m2p = (const float4*)(min_tab + (size_t)i2 * 128) + sub;
    const float4* d2p = (const float4*)(dlt_tab + (size_t)i2 * 128) + sub;

    float p1 = 1.0f, p2 = 1.0f, pm = 1.0f, pj = 1.0f;
    int   EM = 0;
    float mr = 3.4e38f;   // min raw meet extent over my dims

#pragma unroll
    for (int c = 0; c < 4; c++) {
        float4 m1 = __ldg(m1p + c * 8);
        float4 d1 = __ldg(d1p + c * 8);
        float4 m2 = __ldg(m2p + c * 8);
        float4 d2 = __ldg(d2p + c * 8);

        const float* m1v = &m1.x;
        const float* d1v = &d1.x;
        const float* m2v = &m2.x;
        const float* d2v = &d2.x;

#pragma unroll
        for (int j = 0; j < 4; j++) {
            float a  = fmaf(m1v[j], MIN_VAR, MIN_MEAN);     // t1_min
            float da = fmaf(d1v[j], DELTA_VAR, DELTA_MEAN); // t1 extent
            float c0 = fmaf(m2v[j], MIN_VAR, MIN_MEAN);     // t2_min
            float dc = fmaf(d2v[j], DELTA_VAR, DELTA_MEAN); // t2 extent
            float b  = a + da;                              // t1_max
            float d  = c0 + dc;                             // t2_max

            float jmin = fminf(a, c0);
            float jmax = fmaxf(b, d);
            float ej   = jmax - jmin;                 // join extent
            float em   = (da + dc) - ej;              // meet extent (identity)

            mr = fminf(mr, em);
            p1 *= da;
            p2 *= dc;
            pj *= ej;
            pm *= fmaxf(em, EPS_F);
        }
        // only pm can underflow (clamped dims -> 1e-32); renorm per chunk
        pm = split_mant(pm, EM);
    }

    // ratios: per-lane in [~0.4, ~5]; 8-lane products stay fp32-safe.
    // (pm mantissa in [1,2), p2,p1,pj in [~0.4, ~2.3])
    float rm = __fdividef(pm, p2);   // -> meet_log - t2_log (plus EM*ln2)
    float rj = __fdividef(pj, p1);   // -> join_log - t1_log

    const unsigned FULL = 0xFFFFFFFFu;
#pragma unroll
    for (int off = 4; off > 0; off >>= 1) {
        rm *= __shfl_xor_sync(FULL, rm, off);
        rj *= __shfl_xor_sync(FULL, rj, off);
        EM += __shfl_xor_sync(FULL, EM, off);
    }

    // disjoint = any lane in my 8-lane group saw em <= 0
    unsigned ball = __ballot_sync(FULL, mr <= 0.0f);
    bool disjoint = ((ball >> (threadIdx.x & 24)) & 0xFFu) != 0u;

    if (sub == 0) {
        const float LN2 = 0.69314718055994530942f;
        float cond = logf(rm) + (float)EM * LN2;   // log P(t1|t2)

        float posv, negv;
        if (disjoint) {
            posv = logf(rj);                       // join_log - t1_log
            negv = 0.0f;
        } else {
            posv = -cond;
            negv = -logf(fmaxf(1.0f - expf(cond), EPS_F));
        }
        out_pos[pair] = posv;
        out_neg[pair] = negv;
    }
}

extern "C" void kernel_launch(void* const* d_in, const int* in_sizes, int n_in,
                              void* d_out, int out_size) {
    const int*   t1x    = (const int*)d_in[0];
    const int*   t2x    = (const int*)d_in[1];
    const float* min_tb = (const float*)d_in[2];
    const float* dlt_tb = (const float*)d_in[3];

    int B = in_sizes[0];
    float* out_pos = (float*)d_out;
    float* out_neg = (float*)d_out + B;

    // 8 lanes per pair, 32 pairs per 256-thread block
    int pairs_per_block = 32;
    int grid = (B + pairs_per_block - 1) / pairs_per_block;
    box_pair_kernel<<<grid, 256>>>(t1x, t2x, min_tb, dlt_tb, out_pos, out_neg, B);
}

// round 5
// speedup vs baseline: 1.2927x; 1.0012x over previous
#include <cuda_runtime.h>
#include <cuda_bf16.h>
#include <math.h>

// Box-embedding conditional-probability loss. B pairs, D=128.
// R5: R4 was latency-bound (issue 49% @ occ 85%) with MLP capped at ~4
// in-flight LDG.128 by the 32-reg budget. Restructure into 2 macro-steps
// that batch 8 LDG.128 before computing (32 data regs in flight),
// __launch_bounds__(256,6) to allow ~42 regs -> 48 warps/SM.

#define EPS_F 1e-8f

static __device__ __forceinline__ float split_mant(float p, int& e) {
    int ib = __float_as_int(p);
    e += ((ib >> 23) & 0xFF) - 127;
    return __int_as_float((ib & 0x007FFFFF) | 0x3F800000);  // [1,2)
}

__global__ void __launch_bounds__(256, 6)
box_pair_kernel(const int* __restrict__ t1x,
                const int* __restrict__ t2x,
                const float* __restrict__ min_tab,
                const float* __restrict__ dlt_tab,
                float* __restrict__ out_pos,
                float* __restrict__ out_neg,
                int B)
{
    const float MIN_MEAN   = (float)((0.0001 + 0.01) / 2.0);
    const float MIN_VAR    = (float)(0.01 - (0.0001 + 0.01) / 2.0);
    const float DELTA_MEAN = (float)((0.9 + 0.999) / 2.0);
    const float DELTA_VAR  = (float)(0.999 - (0.9 + 0.999) / 2.0);

    int gtid = blockIdx.x * blockDim.x + threadIdx.x;
    int pair = gtid >> 3;           // 8 lanes per pair
    int sub  = threadIdx.x & 7;
    if (pair >= B) return;

    int i1 = __ldg(t1x + pair);
    int i2 = __ldg(t2x + pair);

    const float4* m1p = (const float4*)(min_tab + (size_t)i1 * 128) + sub;
    const float4* d1p = (const float4*)(dlt_tab + (size_t)i1 * 128) + sub;
    const float4* m2p = (const float4*)(min_tab + (size_t)i2 * 128) + sub;
    const float4* d2p = (const float4*)(dlt_tab + (size_t)i2 * 128) + sub;

    float p1 = 1.0f, p2 = 1.0f, pm = 1.0f, pj = 1.0f;
    int   EM = 0;
    float mr = 3.4e38f;   // min raw meet extent over my dims

#pragma unroll
    for (int c2 = 0; c2 < 2; c2++) {
        // batch 8 independent LDG.128 before any consumption (MLP_p1 = 8)
        float4 m1a = __ldg(m1p + (2 * c2 + 0) * 8);
        float4 d1a = __ldg(d1p + (2 * c2 + 0) * 8);
        float4 m2a = __ldg(m2p + (2 * c2 + 0) * 8);
        float4 d2a = __ldg(d2p + (2 * c2 + 0) * 8);
        float4 m1b = __ldg(m1p + (2 * c2 + 1) * 8);
        float4 d1b = __ldg(d1p + (2 * c2 + 1) * 8);
        float4 m2b = __ldg(m2p + (2 * c2 + 1) * 8);
        float4 d2b = __ldg(d2p + (2 * c2 + 1) * 8);

        const float4* M1[2] = { &m1a, &m1b };
        const float4* D1[2] = { &d1a, &d1b };
        const float4* M2[2] = { &m2a, &m2b };
        const float4* D2[2] = { &d2a, &d2b };

#pragma unroll
        for (int h = 0; h < 2; h++) {
            const float* m1v = (const float*)M1[h];
            const float* d1v = (const float*)D1[h];
            const float* m2v = (const float*)M2[h];
            const float* d2v = (const float*)D2[h];
#pragma unroll
            for (int j = 0; j < 4; j++) {
                float a  = fmaf(m1v[j], MIN_VAR, MIN_MEAN);     // t1_min
                float da = fmaf(d1v[j], DELTA_VAR, DELTA_MEAN); // t1 extent
                float c0 = fmaf(m2v[j], MIN_VAR, MIN_MEAN);     // t2_min
                float dc = fmaf(d2v[j], DELTA_VAR, DELTA_MEAN); // t2 extent
                float b  = a + da;                              // t1_max
                float d  = c0 + dc;                             // t2_max

                float jmin = fminf(a, c0);
                float jmax = fmaxf(b, d);
                float ej   = jmax - jmin;             // join extent
                float em   = (da + dc) - ej;          // meet extent (identity)

                mr = fminf(mr, em);
                p1 *= da;
                p2 *= dc;
                pj *= ej;
                pm *= fmaxf(em, EPS_F);
            }
            // pm can reach 1e-32 per 4 clamped dims; renorm keeps it normal
            pm = split_mant(pm, EM);
        }
    }

    // ratios: outputs only need (meet - t2) and (join - t1) log-differences
    float rm = __fdividef(pm, p2);
    float rj = __fdividef(pj, p1);

    const unsigned FULL = 0xFFFFFFFFu;
#pragma unroll
    for (int off = 4; off > 0; off >>= 1) {
        rm *= __shfl_xor_sync(FULL, rm, off);
        rj *= __shfl_xor_sync(FULL, rj, off);
        EM += __shfl_xor_sync(FULL, EM, off);
    }

    // disjoint = any lane in my 8-lane group saw em <= 0
    unsigned ball = __ballot_sync(FULL, mr <= 0.0f);
    bool disjoint = ((ball >> (threadIdx.x & 24)) & 0xFFu) != 0u;

    if (sub == 0) {
        const float LN2 = 0.69314718055994530942f;
        float cond = logf(rm) + (float)EM * LN2;   // log P(t1|t2)

        float posv, negv;
        if (disjoint) {
            posv = logf(rj);                       // join_log - t1_log
            negv = 0.0f;
        } else {
            posv = -cond;
            negv = -logf(fmaxf(1.0f - expf(cond), EPS_F));
        }
        out_pos[pair] = posv;
        out_neg[pair] = negv;
    }
}

extern "C" void kernel_launch(void* const* d_in, const int* in_sizes, int n_in,
                              void* d_out, int out_size) {
    const int*   t1x    = (const int*)d_in[0];
    const int*   t2x    = (const int*)d_in[1];
    const float* min_tb = (const float*)d_in[2];
    const float* dlt_tb = (const float*)d_in[3];

    int B = in_sizes[0];
    float* out_pos = (float*)d_out;
    float* out_neg = (float*)d_out + B;

    // 8 lanes per pair, 32 pairs per 256-thread block
    int pairs_per_block = 32;
    int grid = (B + pairs_per_block - 1) / pairs_per_block;
    box_pair_kernel<<<grid, 256>>>(t1x, t2x, min_tb, dlt_tb, out_pos, out_neg, B);
}